// round 9
// baseline (speedup 1.0000x reference)
#include <cuda_runtime.h>
#include <math_constants.h>
#include <math.h>

// Scratch (no allocs allowed): per-block max partials + global 1/max.
#define MAX_BLOCKS 8192
__device__ float g_partial[MAX_BLOCKS];
__device__ float g_invmax;

typedef unsigned long long u64;

__device__ __forceinline__ float hw_tanh(float x) {
    float r;
    asm("tanh.approx.f32 %0, %1;" : "=f"(r) : "f"(x));
    return r;
}

// ---- packed f32x2 helpers (sm_100+; ptxas only emits these via PTX) ----
__device__ __forceinline__ u64 pk2(float lo, float hi) {
    u64 r; asm("mov.b64 %0, {%1, %2};" : "=l"(r) : "f"(lo), "f"(hi)); return r;
}
__device__ __forceinline__ void upk2(u64 v, float& lo, float& hi) {
    asm("mov.b64 {%0, %1}, %2;" : "=f"(lo), "=f"(hi) : "l"(v));
}
__device__ __forceinline__ u64 add2(u64 a, u64 b) {
    u64 r; asm("add.rn.f32x2 %0, %1, %2;" : "=l"(r) : "l"(a), "l"(b)); return r;
}
__device__ __forceinline__ u64 mul2(u64 a, u64 b) {
    u64 r; asm("mul.rn.f32x2 %0, %1, %2;" : "=l"(r) : "l"(a), "l"(b)); return r;
}
__device__ __forceinline__ u64 fma2(u64 a, u64 b, u64 c) {
    u64 r; asm("fma.rn.f32x2 %0, %1, %2, %3;" : "=l"(r) : "l"(a), "l"(b), "l"(c)); return r;
}

// Rare-path correction: tanh(k*cross)*theta_clamped - sign(cross)*theta_true
__device__ __forceinline__ float corr_term(float dx0, float dy0,
                                           float dx1, float dy1, float crossv) {
    const float k = 100000.0f;
    const float ANG_LO = 4.472136e-3f;   // acos(1-1e-5)
    const float ANG_HI = 3.1371205f;     // pi - acos(1-1e-5)
    float dotv = fmaf(dx0, dx1, dy0 * dy1);
    float ay = fabsf(crossv);
    float ax = fabsf(dotv);
    float num = fminf(ax, ay);
    float den = fmaxf(fmaxf(ax, ay), 1e-37f);
    float a = __fdividef(num, den);
    bool big = a > 0.41421356f;
    float ar = __fdividef(a - 1.0f, a + 1.0f);
    float xx = big ? ar : a;
    float z = xx * xx;
    float pl = fmaf(fmaf(fmaf(8.05374449538e-2f, z,
                              -1.38776856032e-1f), z,
                         1.99777106478e-1f), z,
                    -3.33329491539e-1f);
    float r = fmaf(xx * z, pl, xx);
    if (big) r += 0.78539816340f;
    if (ay > ax) r = 1.57079632679f - r;
    if (dotv < 0.0f) r = 3.14159265359f - r;
    float rc = fminf(fmaxf(r, ANG_LO), ANG_HI);
    float sgn = hw_tanh(k * crossv);
    float signed_t = (crossv < 0.0f) ? -r : r;
    return fmaf(sgn, rc, -signed_t);
}

// Kernel 1: TWO pixels per thread, packed f32x2 fast path.
// Fast path: integer winding via ray-crossing; slow path (rare): correction.
__global__ __launch_bounds__(64) void prod_kernel(
    const float2* __restrict__ contour, int N,
    int Sv, float invS, float* __restrict__ out) {
    extern __shared__ char smem_raw[];
    // scp[j] = (cx,cx,cy,cy) as 2 packed f32x2 ; scn[j] = (-cx,-cx) packed
    ulonglong2* scp = (ulonglong2*)smem_raw;
    u64* scn = (u64*)(smem_raw + (size_t)(N + 1) * 16);
    __shared__ float warp_red[2];

    const int tid = threadIdx.x;
    for (int i = tid; i <= N; i += blockDim.x) {
        float2 c = contour[i == N ? 0 : i];
        scp[i] = make_ulonglong2(pk2(c.x, c.x), pk2(c.y, c.y));
        scn[i] = pk2(-c.x, -c.x);
    }
    __syncthreads();

    const int gid = blockIdx.x * blockDim.x + tid;
    const int p0 = 2 * gid;
    const int npix = Sv * Sv;
    float valA = -CUDART_INF_F, valB = -CUDART_INF_F;

    if (p0 + 1 < npix) {
        const float pxA = (float)(p0 / Sv) * invS;
        const float pyA = (float)(p0 % Sv) * invS;
        const int p1 = p0 + 1;
        const float pxB = (float)(p1 / Sv) * invS;
        const float pyB = (float)(p1 % Sv) * invS;

        const u64 npxv = pk2(-pxA, -pxB);
        const u64 npyv = pk2(-pyA, -pyB);
        const u64 pxv  = pk2(pxA, pxB);
        const u64 HC2  = pk2(2.30e-3f, 2.30e-3f);
        const float CMIN = 1.0e-4f;

        // vertex 0
        ulonglong2 cc0 = scp[0];
        u64 ncx0 = scn[0];
        u64 dx0v  = add2(cc0.x, npxv);
        u64 dy0v  = add2(cc0.y, npyv);
        u64 ndx0v = add2(ncx0, pxv);
        u64 d2pv  = fma2(dx0v, dx0v, mul2(dy0v, dy0v));

        float d2A0, d2B0; upk2(d2pv, d2A0, d2B0);
        float mnA = d2A0, mnB = d2B0;
        float dyA0i, dyB0i; upk2(dy0v, dyA0i, dyB0i);
        bool gA0 = dyA0i > 0.0f;
        bool gB0 = dyB0i > 0.0f;

        int WA = 0, WB = 0;
        float wcA = 0.0f, wcB = 0.0f;

        #pragma unroll 8
        for (int j = 0; j < N; j++) {
            ulonglong2 cc = scp[j + 1];
            u64 ncx = scn[j + 1];
            u64 dxv  = add2(cc.x, npxv);
            u64 dyv  = add2(cc.y, npyv);
            u64 ndxv = add2(ncx, pxv);
            u64 d2v  = fma2(dxv, dxv, mul2(dyv, dyv));
            // cross = dy0*dx1 - dx0*dy1 = fma(ndx0, dy1, dy0*dx1)
            u64 crv  = fma2(ndx0v, dyv, mul2(dy0v, dxv));

            float d2A, d2B; upk2(d2v, d2A, d2B);
            mnA = fminf(mnA, d2A);
            mnB = fminf(mnB, d2B);

            float cA, cB;   upk2(crv, cA, cB);
            float dyA1, dyB1; upk2(dyv, dyA1, dyB1);

            bool gA1 = dyA1 > 0.0f;
            if (gA0 != gA1) {
                if (gA0) { if (cA > 0.0f) WA++; }
                else     { if (cA < 0.0f) WA--; }
            }
            bool gB1 = dyB1 > 0.0f;
            if (gB0 != gB1) {
                if (gB0) { if (cB > 0.0f) WB++; }
                else     { if (cB < 0.0f) WB--; }
            }

            u64 sv = add2(d2pv, d2v);
            u64 tauv = mul2(sv, HC2);
            float tA, tB; upk2(tauv, tA, tB);
            tA = fmaxf(tA, CMIN);
            tB = fmaxf(tB, CMIN);

            bool trgA = fabsf(cA) < tA;
            bool trgB = fabsf(cB) < tB;
            if (trgA || trgB) {
                float dxA0, dxB0; upk2(dx0v, dxA0, dxB0);
                float dyA0, dyB0; upk2(dy0v, dyA0, dyB0);
                float dxA1, dxB1; upk2(dxv, dxA1, dxB1);
                if (trgA) wcA += corr_term(dxA0, dyA0, dxA1, dyA1, cA);
                if (trgB) wcB += corr_term(dxB0, dyB0, dxB1, dyB1, cB);
            }

            dx0v = dxv; dy0v = dyv; ndx0v = ndxv; d2pv = d2v;
            gA0 = gA1; gB0 = gB1;
        }

        float wsA = fmaf(6.283185307179586f, (float)WA, wcA);
        float wsB = fmaf(6.283185307179586f, (float)WB, wcB);
        valA = wsA * 0.15915494309189535f * sqrtf(mnA);
        valB = wsB * 0.15915494309189535f * sqrtf(mnB);
        float2 v2 = make_float2(valA, valB);
        *(float2*)(out + p0) = v2;
    } else if (p0 < npix) {
        // odd-npix tail: single pixel, scalar (never hit for even S^2)
        const float px = (float)(p0 / Sv) * invS;
        const float py = (float)(p0 % Sv) * invS;
        float cx0, cxx0, cy0, cyy0;
        upk2(scp[0].x, cx0, cxx0); upk2(scp[0].y, cy0, cyy0);
        float dx0 = cx0 - px, dy0 = cy0 - py;
        float d2p = fmaf(dx0, dx0, dy0 * dy0);
        float mn2 = d2p; int W = 0; float wc = 0.0f;
        for (int j = 0; j < N; j++) {
            float cx1, t0, cy1, t1;
            upk2(scp[j + 1].x, cx1, t0); upk2(scp[j + 1].y, cy1, t1);
            float dx1 = cx1 - px, dy1 = cy1 - py;
            float d2 = fmaf(dx1, dx1, dy1 * dy1);
            mn2 = fminf(mn2, d2);
            float crossv = dy0 * dx1 - dx0 * dy1;
            bool g0 = dy0 > 0.0f, g1 = dy1 > 0.0f;
            if (g0 != g1) {
                if (g0) { if (crossv > 0.0f) W++; }
                else    { if (crossv < 0.0f) W--; }
            }
            float tau = fmaxf(1.0e-4f, (d2p + d2) * 2.30e-3f);
            if (fabsf(crossv) < tau)
                wc += corr_term(dx0, dy0, dx1, dy1, crossv);
            dx0 = dx1; dy0 = dy1; d2p = d2;
        }
        valA = fmaf(6.283185307179586f, (float)W, wc)
               * 0.15915494309189535f * sqrtf(mn2);
        out[p0] = valA;
    }

    // Block max reduction (2 warps)
    float m = fmaxf(valA, valB);
    #pragma unroll
    for (int o = 16; o > 0; o >>= 1)
        m = fmaxf(m, __shfl_xor_sync(0xffffffffu, m, o));
    if ((tid & 31) == 0) warp_red[tid >> 5] = m;
    __syncthreads();
    if (tid == 0)
        g_partial[blockIdx.x] = fmaxf(warp_red[0], warp_red[1]);
}

// Kernel 2: reduce block partials -> 1/max (single block).
__global__ void max_kernel(int nb) {
    __shared__ float red[32];
    float m = -CUDART_INF_F;
    for (int i = threadIdx.x; i < nb; i += blockDim.x)
        m = fmaxf(m, g_partial[i]);
    #pragma unroll
    for (int o = 16; o > 0; o >>= 1)
        m = fmaxf(m, __shfl_xor_sync(0xffffffffu, m, o));
    if ((threadIdx.x & 31) == 0) red[threadIdx.x >> 5] = m;
    __syncthreads();
    if (threadIdx.x == 0) {
        float bm = red[0];
        int nw = blockDim.x >> 5;
        for (int i = 1; i < nw; i++) bm = fmaxf(bm, red[i]);
        g_invmax = 1.0f / bm;
    }
}

// Kernel 3: normalize (vectorized float4; block 0 covers scalar tail).
__global__ void norm_kernel(float4* __restrict__ out4, float* __restrict__ outf,
                            int nvec, int npix) {
    const float inv = g_invmax;
    int i = blockIdx.x * blockDim.x + threadIdx.x;
    if (i < nvec) {
        float4 v = out4[i];
        v.x *= inv; v.y *= inv; v.z *= inv; v.w *= inv;
        out4[i] = v;
    }
    int tail = npix - nvec * 4;
    if (blockIdx.x == 0 && threadIdx.x < tail)
        outf[nvec * 4 + threadIdx.x] *= inv;
}

extern "C" void kernel_launch(void* const* d_in, const int* in_sizes, int n_in,
                              void* d_out, int out_size) {
    const float2* contour = (const float2*)d_in[0];
    const int N = in_sizes[0] / 2;   // (N, 2) float32
    int Sv = (int)(sqrt((double)out_size) + 0.5);
    float invS = 1.0f / (float)Sv;
    int npix = Sv * Sv;

    float* out = (float*)d_out;
    int threads = 64;
    int pix_per_block = threads * 2;
    int blocks = (npix + pix_per_block - 1) / pix_per_block;  // 1152 for S=384
    size_t smem = (size_t)(N + 1) * (16 + 8);

    prod_kernel<<<blocks, threads, smem>>>(contour, N, Sv, invS, out);
    max_kernel<<<1, 1024>>>(blocks);

    int nvec = npix / 4;
    int nthr = 256;
    int vb = (nvec + nthr - 1) / nthr;
    if (vb < 1) vb = 1;
    norm_kernel<<<vb, nthr>>>((float4*)out, out, nvec, npix);
}

// round 11
// speedup vs baseline: 1.0593x; 1.0593x over previous
#include <cuda_runtime.h>
#include <math_constants.h>
#include <math.h>

// Scratch (no allocs allowed): per-block max partials + global 1/max.
#define MAX_BLOCKS 8192
__device__ float g_partial[MAX_BLOCKS];
__device__ float g_invmax;

__device__ __forceinline__ float hw_tanh(float x) {
    float r;
    asm("tanh.approx.f32 %0, %1;" : "=f"(r) : "f"(x));
    return r;
}

// Rare-path correction: tanh(k*cross)*theta_clamped - sign(cross)*theta_true
__device__ __forceinline__ float corr_term(float dx0, float dy0,
                                           float dx1, float dy1, float crossv) {
    const float k = 100000.0f;
    const float ANG_LO = 4.472136e-3f;   // acos(1-1e-5)
    const float ANG_HI = 3.1371205f;     // pi - acos(1-1e-5)
    float dotv = fmaf(dx0, dx1, dy0 * dy1);
    float ay = fabsf(crossv);
    float ax = fabsf(dotv);
    float num = fminf(ax, ay);
    float den = fmaxf(fmaxf(ax, ay), 1e-37f);
    float a = __fdividef(num, den);
    bool big = a > 0.41421356f;
    float ar = __fdividef(a - 1.0f, a + 1.0f);
    float xx = big ? ar : a;
    float z = xx * xx;
    float pl = fmaf(fmaf(fmaf(8.05374449538e-2f, z,
                              -1.38776856032e-1f), z,
                         1.99777106478e-1f), z,
                    -3.33329491539e-1f);
    float r = fmaf(xx * z, pl, xx);
    if (big) r += 0.78539816340f;
    if (ay > ax) r = 1.57079632679f - r;
    if (dotv < 0.0f) r = 3.14159265359f - r;
    float rc = fminf(fmaxf(r, ANG_LO), ANG_HI);
    float sgn = hw_tanh(k * crossv);
    float signed_t = (crossv < 0.0f) ? -r : r;
    return fmaf(sgn, rc, -signed_t);
}

// Pair kernel: each thread handles two column-adjacent pixels (same row,
// requires Sv even). dx (= c.x - px) and dx^2 are shared between the pair.
__global__ __launch_bounds__(128) void prod_pair_kernel(
    const float2* __restrict__ contour, int N,
    int Sv, float invS, float* __restrict__ out) {
    extern __shared__ float2 sc[];
    __shared__ float warp_red[4];

    const int tid = threadIdx.x;
    for (int i = tid; i <= N; i += blockDim.x)
        sc[i] = contour[i == N ? 0 : i];
    __syncthreads();

    const int gid = blockIdx.x * blockDim.x + tid;
    const int p0 = 2 * gid;
    const int npix = Sv * Sv;
    float valA = -CUDART_INF_F, valB = -CUDART_INF_F;

    if (p0 + 1 < npix) {
        const int row = p0 / Sv;
        const int col = p0 - row * Sv;           // even; col+1 < Sv (Sv even)
        const float px  = (float)row * invS;
        const float pyA = (float)col * invS;
        const float pyB = (float)(col + 1) * invS;
        const float HC = 2.30e-3f;
        const float CMIN = 1.0e-4f;

        float2 c0 = sc[0];
        float dx0  = c0.x - px;
        float dy0A = c0.y - pyA;
        float dy0B = c0.y - pyB;
        float dx0sq = dx0 * dx0;
        float d2pA = fmaf(dy0A, dy0A, dx0sq);
        float d2pB = fmaf(dy0B, dy0B, dx0sq);
        float mnA = d2pA, mnB = d2pB;
        bool gA0 = dy0A > 0.0f;
        bool gB0 = dy0B > 0.0f;
        int WA = 0, WB = 0;
        float wcA = 0.0f, wcB = 0.0f;

        #pragma unroll 4
        for (int j = 0; j < N; j++) {
            float2 c = sc[j + 1];
            float dx1  = c.x - px;               // shared between A/B
            float dy1A = c.y - pyA;
            float dy1B = c.y - pyB;
            float dx1sq = dx1 * dx1;             // shared
            float d2A = fmaf(dy1A, dy1A, dx1sq);
            float d2B = fmaf(dy1B, dy1B, dx1sq);
            mnA = fminf(mnA, d2A);
            mnB = fminf(mnB, d2B);

            // cross = dy0*dx1 - dx0*dy1  (free neg modifier on dx0)
            float cA = fmaf(-dx0, dy1A, dy0A * dx1);
            float cB = fmaf(-dx0, dy1B, dy0B * dx1);

            bool gA1 = dy1A > 0.0f;
            if (gA0 != gA1) {
                if (gA0) { if (cA > 0.0f) WA++; }
                else     { if (cA < 0.0f) WA--; }
            }
            bool gB1 = dy1B > 0.0f;
            if (gB0 != gB1) {
                if (gB0) { if (cB > 0.0f) WB++; }
                else     { if (cB < 0.0f) WB--; }
            }

            // shared conservative trigger: tau >= each pixel's own threshold.
            // spurious triggers are exact no-ops in corr_term.
            float sM = fmaxf(d2pA + d2A, d2pB + d2B);
            float tau = fmaxf(CMIN, sM * HC);
            bool trgA = fabsf(cA) < tau;
            bool trgB = fabsf(cB) < tau;
            if (trgA || trgB) {
                if (trgA) wcA += corr_term(dx0, dy0A, dx1, dy1A, cA);
                if (trgB) wcB += corr_term(dx0, dy0B, dx1, dy1B, cB);
            }

            dx0 = dx1; dy0A = dy1A; dy0B = dy1B;
            d2pA = d2A; d2pB = d2B;
            gA0 = gA1; gB0 = gB1;
        }

        float wsA = fmaf(6.283185307179586f, (float)WA, wcA);
        float wsB = fmaf(6.283185307179586f, (float)WB, wcB);
        valA = wsA * 0.15915494309189535f * sqrtf(mnA);
        valB = wsB * 0.15915494309189535f * sqrtf(mnB);
        *(float2*)(out + p0) = make_float2(valA, valB);
    }

    // Block max reduction
    float m = fmaxf(valA, valB);
    #pragma unroll
    for (int o = 16; o > 0; o >>= 1)
        m = fmaxf(m, __shfl_xor_sync(0xffffffffu, m, o));
    if ((tid & 31) == 0) warp_red[tid >> 5] = m;
    __syncthreads();
    if (tid == 0) {
        float bm = fmaxf(fmaxf(warp_red[0], warp_red[1]),
                         fmaxf(warp_red[2], warp_red[3]));
        g_partial[blockIdx.x] = bm;
    }
}

// Fallback (odd Sv): one pixel per thread — round-6 validated path.
__global__ __launch_bounds__(128) void prod_kernel(
    const float2* __restrict__ contour, int N,
    int Sv, float invS, float* __restrict__ out) {
    extern __shared__ float2 sc[];
    __shared__ float warp_red[4];

    const int tid = threadIdx.x;
    for (int i = tid; i <= N; i += blockDim.x)
        sc[i] = contour[i == N ? 0 : i];
    __syncthreads();

    const int p = blockIdx.x * blockDim.x + tid;
    const int npix = Sv * Sv;
    float val = -CUDART_INF_F;

    if (p < npix) {
        const float px = (float)(p / Sv) * invS;
        const float py = (float)(p % Sv) * invS;
        const float HC = 2.30e-3f;
        const float CMIN = 1.0e-4f;

        float2 c0 = sc[0];
        float dx0 = c0.x - px;
        float dy0 = c0.y - py;
        float d2p = fmaf(dx0, dx0, dy0 * dy0);
        float mn2 = d2p;
        int W = 0;
        float wc = 0.0f;

        #pragma unroll 4
        for (int j = 0; j < N; j++) {
            float2 c = sc[j + 1];
            float dx1 = c.x - px;
            float dy1 = c.y - py;
            float d2 = fmaf(dx1, dx1, dy1 * dy1);
            mn2 = fminf(mn2, d2);
            float crossv = fmaf(dy0, dx1, -dx0 * dy1);
            bool g0 = dy0 > 0.0f, g1 = dy1 > 0.0f;
            if (g0 != g1) {
                if (g0) { if (crossv > 0.0f) W++; }
                else    { if (crossv < 0.0f) W--; }
            }
            float tau = fmaxf(CMIN, (d2p + d2) * HC);
            if (fabsf(crossv) < tau)
                wc += corr_term(dx0, dy0, dx1, dy1, crossv);
            dx0 = dx1; dy0 = dy1; d2p = d2;
        }

        val = fmaf(6.283185307179586f, (float)W, wc)
              * 0.15915494309189535f * sqrtf(mn2);
        out[p] = val;
    }

    float m = val;
    #pragma unroll
    for (int o = 16; o > 0; o >>= 1)
        m = fmaxf(m, __shfl_xor_sync(0xffffffffu, m, o));
    if ((tid & 31) == 0) warp_red[tid >> 5] = m;
    __syncthreads();
    if (tid == 0) {
        float bm = fmaxf(fmaxf(warp_red[0], warp_red[1]),
                         fmaxf(warp_red[2], warp_red[3]));
        g_partial[blockIdx.x] = bm;
    }
}

// Kernel 2: reduce block partials -> 1/max (single block).
__global__ void max_kernel(int nb) {
    __shared__ float red[32];
    float m = -CUDART_INF_F;
    for (int i = threadIdx.x; i < nb; i += blockDim.x)
        m = fmaxf(m, g_partial[i]);
    #pragma unroll
    for (int o = 16; o > 0; o >>= 1)
        m = fmaxf(m, __shfl_xor_sync(0xffffffffu, m, o));
    if ((threadIdx.x & 31) == 0) red[threadIdx.x >> 5] = m;
    __syncthreads();
    if (threadIdx.x == 0) {
        float bm = red[0];
        int nw = blockDim.x >> 5;
        for (int i = 1; i < nw; i++) bm = fmaxf(bm, red[i]);
        g_invmax = 1.0f / bm;
    }
}

// Kernel 3: normalize (vectorized float4; block 0 covers scalar tail).
__global__ void norm_kernel(float4* __restrict__ out4, float* __restrict__ outf,
                            int nvec, int npix) {
    const float inv = g_invmax;
    int i = blockIdx.x * blockDim.x + threadIdx.x;
    if (i < nvec) {
        float4 v = out4[i];
        v.x *= inv; v.y *= inv; v.z *= inv; v.w *= inv;
        out4[i] = v;
    }
    int tail = npix - nvec * 4;
    if (blockIdx.x == 0 && threadIdx.x < tail)
        outf[nvec * 4 + threadIdx.x] *= inv;
}

extern "C" void kernel_launch(void* const* d_in, const int* in_sizes, int n_in,
                              void* d_out, int out_size) {
    const float2* contour = (const float2*)d_in[0];
    const int N = in_sizes[0] / 2;   // (N, 2) float32
    int Sv = (int)(sqrt((double)out_size) + 0.5);
    float invS = 1.0f / (float)Sv;
    int npix = Sv * Sv;

    float* out = (float*)d_out;
    size_t smem = (size_t)(N + 1) * sizeof(float2);
    int blocks;

    if ((Sv & 1) == 0) {
        int threads = 128;
        int pix_per_block = threads * 2;
        blocks = (npix + pix_per_block - 1) / pix_per_block;  // 576 for S=384
        prod_pair_kernel<<<blocks, threads, smem>>>(contour, N, Sv, invS, out);
    } else {
        int threads = 128;
        blocks = (npix + threads - 1) / threads;
        prod_kernel<<<blocks, threads, smem>>>(contour, N, Sv, invS, out);
    }

    max_kernel<<<1, 1024>>>(blocks);

    int nvec = npix / 4;
    int nthr = 256;
    int vb = (nvec + nthr - 1) / nthr;
    if (vb < 1) vb = 1;
    norm_kernel<<<vb, nthr>>>((float4*)out, out, nvec, npix);
}

// round 13
// speedup vs baseline: 1.0601x; 1.0008x over previous
#include <cuda_runtime.h>
#include <math_constants.h>
#include <math.h>

// Scratch (no allocs allowed): per-block max partials + global 1/max.
#define MAX_BLOCKS 8192
__device__ float g_partial[MAX_BLOCKS];
__device__ float g_invmax;

__device__ __forceinline__ float hw_tanh(float x) {
    float r;
    asm("tanh.approx.f32 %0, %1;" : "=f"(r) : "f"(x));
    return r;
}

// Rare-path correction: tanh(k*cross)*theta_clamped - sign(cross)*theta_true
__device__ __forceinline__ float corr_term(float dx0, float dy0,
                                           float dx1, float dy1, float crossv) {
    const float k = 100000.0f;
    const float ANG_LO = 4.472136e-3f;   // acos(1-1e-5)
    const float ANG_HI = 3.1371205f;     // pi - acos(1-1e-5)
    float dotv = fmaf(dx0, dx1, dy0 * dy1);
    float ay = fabsf(crossv);
    float ax = fabsf(dotv);
    float num = fminf(ax, ay);
    float den = fmaxf(fmaxf(ax, ay), 1e-37f);
    float a = __fdividef(num, den);
    bool big = a > 0.41421356f;
    float ar = __fdividef(a - 1.0f, a + 1.0f);
    float xx = big ? ar : a;
    float z = xx * xx;
    float pl = fmaf(fmaf(fmaf(8.05374449538e-2f, z,
                              -1.38776856032e-1f), z,
                         1.99777106478e-1f), z,
                    -3.33329491539e-1f);
    float r = fmaf(xx * z, pl, xx);
    if (big) r += 0.78539816340f;
    if (ay > ax) r = 1.57079632679f - r;
    if (dotv < 0.0f) r = 3.14159265359f - r;
    float rc = fminf(fmaxf(r, ANG_LO), ANG_HI);
    float sgn = hw_tanh(k * crossv);
    float signed_t = (crossv < 0.0f) ? -r : r;
    return fmaf(sgn, rc, -signed_t);
}

// Kernel 1: one pixel per thread. Integer winding by ray-crossing (fast),
// rare slow-path correction where tanh unsaturated / acos clamp active.
// Edge records in smem: rec[j] = (c_{j+1}.x, c_{j+1}.y, e_j.x, e_j.y).
__global__ __launch_bounds__(128) void prod_kernel(
    const float2* __restrict__ contour, int N,
    int Sv, float invS, float* __restrict__ out) {
    extern __shared__ float4 rec[];
    __shared__ float warp_red[4];
    __shared__ float2 s_c0;

    const int tid = threadIdx.x;
    for (int i = tid; i < N; i += blockDim.x) {
        float2 ca = contour[i];
        float2 cb = contour[(i + 1 < N) ? i + 1 : 0];
        rec[i] = make_float4(cb.x, cb.y, cb.x - ca.x, cb.y - ca.y);
    }
    if (tid == 0) s_c0 = contour[0];
    __syncthreads();

    const int p = blockIdx.x * blockDim.x + tid;
    const int npix = Sv * Sv;
    float val = -CUDART_INF_F;

    if (p < npix) {
        const float px = (float)(p / Sv) * invS;
        const float py = (float)(p % Sv) * invS;
        // exact clamp coverage: cross^2 < K2 * d2p * d2
        //   K2 = sin^2(acos(1-1e-5)) * margin = 2.0e-5 * 1.05
        const float K2 = 2.1e-5f;
        // tanh coverage: |cross| < 1e-4  ->  cross^2 < 1e-8 (+margin)
        const float CMIN2 = 1.1e-8f;

        float2 c0 = s_c0;
        float dx0 = c0.x - px;
        float dy0 = c0.y - py;
        float d2p = fmaf(dx0, dx0, dy0 * dy0);
        float mn2 = d2p;
        bool g0 = dy0 > 0.0f;
        int W = 0;
        float wc = 0.0f;

        #pragma unroll 8
        for (int j = 0; j < N; j++) {
            float4 r = rec[j];
            // cross(diff_j, e_j) == cross(diff_j, diff_{j+1}) exactly (algebra)
            float crossv = fmaf(dy0, r.z, -dx0 * r.w);
            float dx1 = r.x - px;
            float dy1 = r.y - py;
            float d2 = fmaf(dx1, dx1, dy1 * dy1);
            mn2 = fminf(mn2, d2);

            bool g1 = dy1 > 0.0f;
            if (g0 != g1) {
                if (g0) { if (crossv > 0.0f) W++; }
                else    { if (crossv < 0.0f) W--; }
            }

            float cr2 = crossv * crossv;
            float tau2 = fmaxf(CMIN2, K2 * (d2p * d2));
            if (cr2 < tau2)
                wc += corr_term(dx0, dy0, dx1, dy1, crossv);

            dx0 = dx1; dy0 = dy1; d2p = d2; g0 = g1;
        }

        val = fmaf(6.283185307179586f, (float)W, wc)
              * 0.15915494309189535f * sqrtf(mn2);
        out[p] = val;
    }

    // Block max reduction
    float m = val;
    #pragma unroll
    for (int o = 16; o > 0; o >>= 1)
        m = fmaxf(m, __shfl_xor_sync(0xffffffffu, m, o));
    if ((tid & 31) == 0) warp_red[tid >> 5] = m;
    __syncthreads();
    if (tid == 0) {
        float bm = fmaxf(fmaxf(warp_red[0], warp_red[1]),
                         fmaxf(warp_red[2], warp_red[3]));
        g_partial[blockIdx.x] = bm;
    }
}

// Kernel 2: reduce block partials -> 1/max (single block).
__global__ void max_kernel(int nb) {
    __shared__ float red[32];
    float m = -CUDART_INF_F;
    for (int i = threadIdx.x; i < nb; i += blockDim.x)
        m = fmaxf(m, g_partial[i]);
    #pragma unroll
    for (int o = 16; o > 0; o >>= 1)
        m = fmaxf(m, __shfl_xor_sync(0xffffffffu, m, o));
    if ((threadIdx.x & 31) == 0) red[threadIdx.x >> 5] = m;
    __syncthreads();
    if (threadIdx.x == 0) {
        float bm = red[0];
        int nw = blockDim.x >> 5;
        for (int i = 1; i < nw; i++) bm = fmaxf(bm, red[i]);
        g_invmax = 1.0f / bm;
    }
}

// Kernel 3: normalize (vectorized float4; block 0 covers scalar tail).
__global__ void norm_kernel(float4* __restrict__ out4, float* __restrict__ outf,
                            int nvec, int npix) {
    const float inv = g_invmax;
    int i = blockIdx.x * blockDim.x + threadIdx.x;
    if (i < nvec) {
        float4 v = out4[i];
        v.x *= inv; v.y *= inv; v.z *= inv; v.w *= inv;
        out4[i] = v;
    }
    int tail = npix - nvec * 4;
    if (blockIdx.x == 0 && threadIdx.x < tail)
        outf[nvec * 4 + threadIdx.x] *= inv;
}

extern "C" void kernel_launch(void* const* d_in, const int* in_sizes, int n_in,
                              void* d_out, int out_size) {
    const float2* contour = (const float2*)d_in[0];
    const int N = in_sizes[0] / 2;   // (N, 2) float32
    int Sv = (int)(sqrt((double)out_size) + 0.5);
    float invS = 1.0f / (float)Sv;
    int npix = Sv * Sv;

    float* out = (float*)d_out;
    int threads = 128;
    int blocks = (npix + threads - 1) / threads;   // 1152 for S=384
    size_t smem = (size_t)N * sizeof(float4);

    prod_kernel<<<blocks, threads, smem>>>(contour, N, Sv, invS, out);
    max_kernel<<<1, 1024>>>(blocks);

    int nvec = npix / 4;
    int nthr = 256;
    int vb = (nvec + nthr - 1) / nthr;
    if (vb < 1) vb = 1;
    norm_kernel<<<vb, nthr>>>((float4*)out, out, nvec, npix);
}

// round 14
// speedup vs baseline: 1.1831x; 1.1160x over previous
#include <cuda_runtime.h>
#include <math_constants.h>
#include <math.h>

// Scratch (no allocs allowed): per-block max partials + global 1/max.
#define MAX_BLOCKS 8192
__device__ float g_partial[MAX_BLOCKS];
__device__ float g_invmax;

__device__ __forceinline__ float hw_tanh(float x) {
    float r;
    asm("tanh.approx.f32 %0, %1;" : "=f"(r) : "f"(x));
    return r;
}

// Rare-path correction: tanh(k*cross)*theta_clamped - sign(cross)*theta_true
__device__ __forceinline__ float corr_term(float dx0, float dy0,
                                           float dx1, float dy1, float crossv) {
    const float k = 100000.0f;
    const float ANG_LO = 4.472136e-3f;   // acos(1-1e-5)
    const float ANG_HI = 3.1371205f;     // pi - acos(1-1e-5)
    float dotv = fmaf(dx0, dx1, dy0 * dy1);
    float ay = fabsf(crossv);
    float ax = fabsf(dotv);
    float num = fminf(ax, ay);
    float den = fmaxf(fmaxf(ax, ay), 1e-37f);
    float a = __fdividef(num, den);
    bool big = a > 0.41421356f;
    float ar = __fdividef(a - 1.0f, a + 1.0f);
    float xx = big ? ar : a;
    float z = xx * xx;
    float pl = fmaf(fmaf(fmaf(8.05374449538e-2f, z,
                              -1.38776856032e-1f), z,
                         1.99777106478e-1f), z,
                    -3.33329491539e-1f);
    float r = fmaf(xx * z, pl, xx);
    if (big) r += 0.78539816340f;
    if (ay > ax) r = 1.57079632679f - r;
    if (dotv < 0.0f) r = 3.14159265359f - r;
    float rc = fminf(fmaxf(r, ANG_LO), ANG_HI);
    float sgn = hw_tanh(k * crossv);
    float signed_t = (crossv < 0.0f) ? -r : r;
    return fmaf(sgn, rc, -signed_t);
}

// Kernel 1: TWO threads per pixel, each covering half the vertex pairs.
// Warp-level half assignment keeps sc[j] loads broadcast (conflict-free):
// block = 256 threads = 8 warps; warps 0-3 -> half 0 of 128 pixels,
// warps 4-7 -> half 1 of the same 128 pixels.
__global__ __launch_bounds__(256) void prod_kernel(
    const float2* __restrict__ contour, int N,
    int Sv, float invS, float* __restrict__ out) {
    extern __shared__ char sraw[];
    float4* s_part = (float4*)sraw;                    // 128 combine slots
    float2* sc = (float2*)(sraw + 128 * sizeof(float4)); // N+1 vertices
    __shared__ float warp_red[8];

    const int tid = threadIdx.x;
    for (int i = tid; i <= N; i += blockDim.x)
        sc[i] = contour[i == N ? 0 : i];
    __syncthreads();

    const int warp = tid >> 5;
    const int lane = tid & 31;
    const int half = warp >> 2;                 // 0 or 1
    const int pix_in_blk = ((warp & 3) << 5) + lane;
    const int p = blockIdx.x * 128 + pix_in_blk;
    const int npix = Sv * Sv;
    const int split = N >> 1;
    const int jbeg = half ? split : 0;
    const int jend = half ? N : split;
    const bool active = p < npix;

    float mn2 = CUDART_INF_F, wc = 0.0f;
    int W = 0;
    float val = -CUDART_INF_F;

    if (active) {
        const float px = (float)(p / Sv) * invS;
        const float py = (float)(p % Sv) * invS;
        const float HC = 2.30e-3f;
        const float CMIN = 1.0e-4f;

        float2 c0 = sc[jbeg];
        float dx0 = c0.x - px;
        float dy0 = c0.y - py;
        float d2p = fmaf(dx0, dx0, dy0 * dy0);
        mn2 = d2p;
        bool g0 = dy0 > 0.0f;

        #pragma unroll 4
        for (int j = jbeg; j < jend; j++) {
            float2 c = sc[j + 1];
            float dx1 = c.x - px;
            float dy1 = c.y - py;
            float d2 = fmaf(dx1, dx1, dy1 * dy1);
            mn2 = fminf(mn2, d2);
            float crossv = fmaf(dy0, dx1, -dx0 * dy1);

            bool g1 = dy1 > 0.0f;
            if (g0 != g1) {
                if (g0) { if (crossv > 0.0f) W++; }
                else    { if (crossv < 0.0f) W--; }
            }

            // conservative trigger: s*HC + CMIN >= max(CMIN, s*HC);
            // spurious triggers yield exactly-zero corrections.
            float tau = fmaf(d2p + d2, HC, CMIN);
            if (fabsf(crossv) < tau)
                wc += corr_term(dx0, dy0, dx1, dy1, crossv);

            dx0 = dx1; dy0 = dy1; d2p = d2; g0 = g1;
        }
    }

    // Combine the two halves through smem.
    if (half == 1 && active)
        s_part[pix_in_blk] = make_float4(mn2, wc, (float)W, 0.0f);
    __syncthreads();
    if (half == 0 && active) {
        float4 o = s_part[pix_in_blk];
        mn2 = fminf(mn2, o.x);
        wc += o.y;
        W += (int)o.z;
        val = fmaf(6.283185307179586f, (float)W, wc)
              * 0.15915494309189535f * sqrtf(mn2);
        out[p] = val;
    }

    // Block max reduction (half-1 threads hold -inf).
    float m = val;
    #pragma unroll
    for (int o = 16; o > 0; o >>= 1)
        m = fmaxf(m, __shfl_xor_sync(0xffffffffu, m, o));
    if (lane == 0) warp_red[warp] = m;
    __syncthreads();
    if (tid == 0) {
        float bm = warp_red[0];
        #pragma unroll
        for (int i = 1; i < 8; i++) bm = fmaxf(bm, warp_red[i]);
        g_partial[blockIdx.x] = bm;
    }
}

// Kernel 2: reduce block partials -> 1/max (single block).
__global__ void max_kernel(int nb) {
    __shared__ float red[32];
    float m = -CUDART_INF_F;
    for (int i = threadIdx.x; i < nb; i += blockDim.x)
        m = fmaxf(m, g_partial[i]);
    #pragma unroll
    for (int o = 16; o > 0; o >>= 1)
        m = fmaxf(m, __shfl_xor_sync(0xffffffffu, m, o));
    if ((threadIdx.x & 31) == 0) red[threadIdx.x >> 5] = m;
    __syncthreads();
    if (threadIdx.x == 0) {
        float bm = red[0];
        int nw = blockDim.x >> 5;
        for (int i = 1; i < nw; i++) bm = fmaxf(bm, red[i]);
        g_invmax = 1.0f / bm;
    }
}

// Kernel 3: normalize (vectorized float4; block 0 covers scalar tail).
__global__ void norm_kernel(float4* __restrict__ out4, float* __restrict__ outf,
                            int nvec, int npix) {
    const float inv = g_invmax;
    int i = blockIdx.x * blockDim.x + threadIdx.x;
    if (i < nvec) {
        float4 v = out4[i];
        v.x *= inv; v.y *= inv; v.z *= inv; v.w *= inv;
        out4[i] = v;
    }
    int tail = npix - nvec * 4;
    if (blockIdx.x == 0 && threadIdx.x < tail)
        outf[nvec * 4 + threadIdx.x] *= inv;
}

extern "C" void kernel_launch(void* const* d_in, const int* in_sizes, int n_in,
                              void* d_out, int out_size) {
    const float2* contour = (const float2*)d_in[0];
    const int N = in_sizes[0] / 2;   // (N, 2) float32
    int Sv = (int)(sqrt((double)out_size) + 0.5);
    float invS = 1.0f / (float)Sv;
    int npix = Sv * Sv;

    float* out = (float*)d_out;
    int blocks = (npix + 127) / 128;               // 1152 for S=384
    size_t smem = 128 * sizeof(float4) + (size_t)(N + 1) * sizeof(float2);

    prod_kernel<<<blocks, 256, smem>>>(contour, N, Sv, invS, out);
    max_kernel<<<1, 1024>>>(blocks);

    int nvec = npix / 4;
    int nthr = 256;
    int vb = (nvec + nthr - 1) / nthr;
    if (vb < 1) vb = 1;
    norm_kernel<<<vb, nthr>>>((float4*)out, out, nvec, npix);
}